// round 1
// baseline (speedup 1.0000x reference)
#include <cuda_runtime.h>

#define H      2048
#define BSZ    512
#define UD     1024
#define DUD    512
#define KCAT   1536
#define YD     1024
#define DELTA  0.01f

// ---------------- scratch (static device globals; no runtime allocation) ----
__device__ float g_X   [H * H];        // X = delta * antisym(W)
__device__ float g_cat [BSZ * KCAT];   // [du, u]
__device__ float g_b   [BSZ * H];      // cat @ Bw^T
__device__ float g_s1  [BSZ * H];      // NT(b, X)  = -bX
__device__ float g_s2  [BSZ * H];      // NT(s1, X) =  bX^2
__device__ float g_z   [BSZ * H];      // h_new
__device__ float g_rec [H];
__device__ float g_r0  [H];
__device__ float g_r1  [H];
__device__ float g_part[16 * H];

// ---------------- small elementwise kernels ---------------------------------
__global__ void build_X(const float* __restrict__ W, float* __restrict__ X) {
    int idx = blockIdx.x * 256 + threadIdx.x;       // H*H / 256 blocks
    int i = idx >> 11;
    int j = idx & (H - 1);
    // X = 0.5*delta*(W - W^T); transposed read is L2-resident (16MB < 126MB L2)
    X[idx] = (0.5f * DELTA) * (W[idx] - W[j * H + i]);
}

__global__ void init_vec(const float* __restrict__ h,
                         float* __restrict__ rec, float* __restrict__ r0) {
    int j = blockIdx.x * 256 + threadIdx.x;
    float v = h[j];
    rec[j] = v;   // k=0 term of e^{-X}
    r0[j]  = v;
}

__global__ void concat_k(const float* __restrict__ u, const float* __restrict__ du,
                         float* __restrict__ cat) {
    int idx = blockIdx.x * 256 + threadIdx.x;       // BSZ*KCAT / 256 blocks
    int i = idx / KCAT;
    int k = idx - i * KCAT;
    cat[idx] = (k < DUD) ? du[i * DUD + k] : u[i * UD + (k - DUD)];
}

__global__ void combine_z(const float* __restrict__ b, const float* __restrict__ s1,
                          const float* __restrict__ s2, const float* __restrict__ rec,
                          float* __restrict__ z) {
    int idx = blockIdx.x * 256 + threadIdx.x;       // BSZ*H / 256 blocks
    int j = idx & (H - 1);
    // inp = delta*(b - (bX)/2 + (bX^2)/6) ; bX = -s1, bX^2 = s2
    z[idx] = rec[j] + DELTA * (b[idx] + 0.5f * s1[idx] + (1.0f / 6.0f) * s2[idx]);
}

// ---------------- GEMV chain for rec = h @ e^{-X} ---------------------------
// part[c][j] = sum over k-chunk c of x[k] * X[k*H + j]
__global__ void gemv_part(const float* __restrict__ x, const float* __restrict__ X,
                          float* __restrict__ part) {
    __shared__ float xs[128];
    int j  = blockIdx.x * 256 + threadIdx.x;
    int k0 = blockIdx.y * 128;
    if (threadIdx.x < 128) xs[threadIdx.x] = x[k0 + threadIdx.x];
    __syncthreads();
    float acc = 0.f;
#pragma unroll 8
    for (int k = 0; k < 128; k++)
        acc += xs[k] * X[(k0 + k) * H + j];
    part[blockIdx.y * H + j] = acc;
}

__global__ void gemv_reduce(const float* __restrict__ part, float* __restrict__ out,
                            float* __restrict__ rec, float coef) {
    int j = blockIdx.x * 256 + threadIdx.x;
    float s = 0.f;
#pragma unroll
    for (int c = 0; c < 16; c++) s += part[c * H + j];
    out[j] = s;
    rec[j] += coef * s;
}

// ---------------- NT GEMM: C[m,n] = alpha * sum_k A[m*K+k] * B[n*K+k] -------
// 64x64 tile, BK=16, 256 threads, 4x4 microtile, fp32 accumulate.
// Requires M%64==0, N%64==0, K%16==0 (true for all calls).
__global__ void __launch_bounds__(256)
gemm_nt(const float* __restrict__ A, const float* __restrict__ B,
        float* __restrict__ C, int K, int N, float alpha) {
    __shared__ float As[16][68];   // [k][m], padded stride (16B-aligned rows)
    __shared__ float Bs[16][68];   // [k][n]

    const int tid = threadIdx.x;
    const int tx = tid & 15;           // n-quad
    const int ty = tid >> 4;           // m-quad
    const int row0 = blockIdx.y * 64;
    const int col0 = blockIdx.x * 64;

    const int ar = tid >> 2;           // 0..63 (tile row for loads)
    const int ak = (tid & 3) << 2;     // 0,4,8,12 (k offset, float4)

    const float* Aptr = A + (size_t)(row0 + ar) * K + ak;
    const float* Bptr = B + (size_t)(col0 + ar) * K + ak;

    float acc[4][4] = {};

    for (int k0 = 0; k0 < K; k0 += 16) {
        float4 av = *(const float4*)(Aptr + k0);
        float4 bv = *(const float4*)(Bptr + k0);
        As[ak + 0][ar] = av.x; As[ak + 1][ar] = av.y;
        As[ak + 2][ar] = av.z; As[ak + 3][ar] = av.w;
        Bs[ak + 0][ar] = bv.x; Bs[ak + 1][ar] = bv.y;
        Bs[ak + 2][ar] = bv.z; Bs[ak + 3][ar] = bv.w;
        __syncthreads();
#pragma unroll
        for (int k = 0; k < 16; k++) {
            float4 a4 = *(const float4*)&As[k][ty << 2];
            float4 b4 = *(const float4*)&Bs[k][tx << 2];
            float aa[4] = {a4.x, a4.y, a4.z, a4.w};
            float bb[4] = {b4.x, b4.y, b4.z, b4.w};
#pragma unroll
            for (int i = 0; i < 4; i++)
#pragma unroll
                for (int j = 0; j < 4; j++)
                    acc[i][j] += aa[i] * bb[j];
        }
        __syncthreads();
    }

#pragma unroll
    for (int i = 0; i < 4; i++) {
        float4 o = make_float4(alpha * acc[i][0], alpha * acc[i][1],
                               alpha * acc[i][2], alpha * acc[i][3]);
        *(float4*)&C[(size_t)(row0 + (ty << 2) + i) * N + col0 + (tx << 2)] = o;
    }
}

// ---------------- launch -----------------------------------------------------
extern "C" void kernel_launch(void* const* d_in, const int* in_sizes, int n_in,
                              void* d_out, int out_size) {
    const float* u  = (const float*)d_in[0];
    const float* du = (const float*)d_in[1];
    const float* W  = (const float*)d_in[2];
    const float* Bw = (const float*)d_in[3];
    const float* Cw = (const float*)d_in[4];
    const float* h  = (const float*)d_in[5];
    float* y = (float*)d_out;

    float *pX, *pcat, *pb, *ps1, *ps2, *pz, *prec, *pr0, *pr1, *ppart;
    cudaGetSymbolAddress((void**)&pX,    g_X);
    cudaGetSymbolAddress((void**)&pcat,  g_cat);
    cudaGetSymbolAddress((void**)&pb,    g_b);
    cudaGetSymbolAddress((void**)&ps1,   g_s1);
    cudaGetSymbolAddress((void**)&ps2,   g_s2);
    cudaGetSymbolAddress((void**)&pz,    g_z);
    cudaGetSymbolAddress((void**)&prec,  g_rec);
    cudaGetSymbolAddress((void**)&pr0,   g_r0);
    cudaGetSymbolAddress((void**)&pr1,   g_r1);
    cudaGetSymbolAddress((void**)&ppart, g_part);

    build_X <<<(H * H) / 256, 256>>>(W, pX);
    init_vec<<<H / 256, 256>>>(h, prec, pr0);
    concat_k<<<(BSZ * KCAT) / 256, 256>>>(u, du, pcat);

    // rec = h @ e^{-X} = h - hX + hX^2/2 - hX^3/6 + hX^4/24
    const float coefs[4] = {-1.f, 0.5f, -1.f / 6.f, 1.f / 24.f};
    float* bufs[2] = {pr0, pr1};
    for (int s = 0; s < 4; s++) {
        gemv_part  <<<dim3(H / 256, 16), 256>>>(bufs[s & 1], pX, ppart);
        gemv_reduce<<<H / 256, 256>>>(ppart, bufs[(s + 1) & 1], prec, coefs[s]);
    }

    // b = cat @ Bw^T            (512 x 2048, K=1536)
    gemm_nt<<<dim3(H / 64, BSZ / 64), 256>>>(pcat, Bw, pb, KCAT, H, 1.f);
    // s1 = NT(b, X)  = -bX      (512 x 2048, K=2048)
    gemm_nt<<<dim3(H / 64, BSZ / 64), 256>>>(pb, pX, ps1, H, H, 1.f);
    // s2 = NT(s1, X) =  bX^2
    gemm_nt<<<dim3(H / 64, BSZ / 64), 256>>>(ps1, pX, ps2, H, H, 1.f);
    // z = rec + delta*(b + s1/2 + s2/6)
    combine_z<<<(BSZ * H) / 256, 256>>>(pb, ps1, ps2, prec, pz);
    // y = z @ Cw^T              (512 x 1024, K=2048)
    gemm_nt<<<dim3(YD / 64, BSZ / 64), 256>>>(pz, Cw, y, H, YD, 1.f);
}

// round 6
// speedup vs baseline: 3.1419x; 3.1419x over previous
#include <cuda_runtime.h>
#include <cuda_bf16.h>
#include <cstdint>

#define H      2048
#define BSZ    512
#define UD     1024
#define DUD    512
#define KCAT   1536
#define YD     1024
#define DELTA  0.01f

// ---------------- scratch ----------------------------------------------------
__device__ float g_X   [H * H];
__device__ float g_cat [BSZ * KCAT];
__device__ float g_b   [BSZ * H];
__device__ float g_s1  [BSZ * H];
__device__ float g_s2  [BSZ * H];
__device__ float g_d   [BSZ * H];
__device__ float g_rec [H];
__device__ float g_r0  [H];
__device__ float g_r1  [H];
__device__ float g_part[32 * H];
__device__ float g_yrec[YD];

// ---------------- helpers -----------------------------------------------------
__device__ __forceinline__ uint32_t smem_u32(const void* p) {
    uint32_t a;
    asm("{ .reg .u64 t; cvta.to.shared.u64 t, %1; cvt.u32.u64 %0, t; }"
        : "=r"(a) : "l"(p));
    return a;
}
__device__ __forceinline__ void ldsm_x4(uint32_t& r0, uint32_t& r1, uint32_t& r2,
                                        uint32_t& r3, uint32_t a) {
    asm volatile("ldmatrix.sync.aligned.m8n8.x4.shared.b16 {%0,%1,%2,%3}, [%4];"
                 : "=r"(r0), "=r"(r1), "=r"(r2), "=r"(r3) : "r"(a));
}
__device__ __forceinline__ void mma16816(float& c0, float& c1, float& c2, float& c3,
                                         uint32_t a0, uint32_t a1, uint32_t a2, uint32_t a3,
                                         uint32_t b0, uint32_t b1) {
    asm volatile(
        "mma.sync.aligned.m16n8k16.row.col.f32.bf16.bf16.f32 "
        "{%0,%1,%2,%3},{%4,%5,%6,%7},{%8,%9},{%0,%1,%2,%3};"
        : "+f"(c0), "+f"(c1), "+f"(c2), "+f"(c3)
        : "r"(a0), "r"(a1), "r"(a2), "r"(a3), "r"(b0), "r"(b1));
}
__device__ __forceinline__ uint32_t pack_bf2(float a, float b) {
    __nv_bfloat162 p = __floats2bfloat162_rn(a, b);
    return *reinterpret_cast<uint32_t*>(&p);
}

// ---------------- small elementwise kernels ----------------------------------
__global__ void build_X(const float* __restrict__ W, float* __restrict__ X) {
    __shared__ float t[32][33];
    int bx = blockIdx.x * 32, by = blockIdx.y * 32;
    int tx = threadIdx.x, ty = threadIdx.y;            // 32 x 8
#pragma unroll
    for (int i = 0; i < 32; i += 8)
        t[ty + i][tx] = W[(size_t)(bx + ty + i) * H + by + tx];
    __syncthreads();
#pragma unroll
    for (int i = 0; i < 32; i += 8) {
        int r = by + ty + i, c = bx + tx;
        X[(size_t)r * H + c] = (0.5f * DELTA) * (W[(size_t)r * H + c] - t[tx][ty + i]);
    }
}

__global__ void init_vec(const float* __restrict__ h,
                         float* __restrict__ rec, float* __restrict__ r0) {
    int j = blockIdx.x * 256 + threadIdx.x;
    float v = h[j];
    rec[j] = v;
    r0[j] = v;
}

__global__ void concat_k(const float* __restrict__ u, const float* __restrict__ du,
                         float* __restrict__ cat) {
    int idx = blockIdx.x * 256 + threadIdx.x;
    int i = idx / KCAT;
    int k = idx - i * KCAT;
    cat[idx] = (k < DUD) ? du[i * DUD + k] : u[i * UD + (k - DUD)];
}

// d = delta * (b + s1/2 + s2/6)   (small input term only; rec handled as bias)
__global__ void combine_d(const float* __restrict__ b, const float* __restrict__ s1,
                          const float* __restrict__ s2, float* __restrict__ d) {
    int idx = blockIdx.x * 256 + threadIdx.x;
    d[idx] = DELTA * (b[idx] + 0.5f * s1[idx] + (1.0f / 6.0f) * s2[idx]);
}

// ---------------- GEMV chain: rec = h - hX + hX^2/2 ---------------------------
__global__ void gemv_part(const float* __restrict__ x, const float* __restrict__ X,
                          float* __restrict__ part) {
    __shared__ float xs[64];
    int j = blockIdx.x * 256 + threadIdx.x;
    int k0 = blockIdx.y * 64;
    if (threadIdx.x < 64) xs[threadIdx.x] = x[k0 + threadIdx.x];
    __syncthreads();
    float acc = 0.f;
#pragma unroll 16
    for (int k = 0; k < 64; k++)
        acc += xs[k] * X[(size_t)(k0 + k) * H + j];
    part[blockIdx.y * H + j] = acc;
}

__global__ void gemv_reduce(const float* __restrict__ part, float* __restrict__ out,
                            float* __restrict__ rec, float coef) {
    int j = blockIdx.x * 256 + threadIdx.x;
    float s = 0.f;
#pragma unroll
    for (int c = 0; c < 32; c++) s += part[c * H + j];
    out[j] = s;
    rec[j] += coef * s;
}

// yrec[j] = sum_k rec[k] * Cw[j*H + k]   (one warp per output row, fp32 exact)
__global__ void gemv_rows(const float* __restrict__ rec, const float* __restrict__ Cw,
                          float* __restrict__ yrec) {
    int row = blockIdx.x * 8 + (threadIdx.x >> 5);
    int lane = threadIdx.x & 31;
    const float* cr = Cw + (size_t)row * H;
    float s = 0.f;
#pragma unroll
    for (int i = 0; i < 16; i++) {
        float4 c = *(const float4*)(cr + lane * 4 + i * 128);
        float4 r = *(const float4*)(rec + lane * 4 + i * 128);
        s += c.x * r.x + c.y * r.y + c.z * r.z + c.w * r.w;
    }
#pragma unroll
    for (int o = 16; o > 0; o >>= 1) s += __shfl_xor_sync(0xffffffffu, s, o);
    if (lane == 0) yrec[row] = s;
}

// ---------------- bf16 mma.sync NT GEMM ---------------------------------------
// C[m,n] = sum_k A[m*K+k]*B[n*K+k] (+ bias[n]); fp32 in, bf16 mma, fp32 acc.
// CTA tile 128x64, K-chunk 32, 8 warps (2m x 4n), warp tile 64x16.
// SMEM rows padded to 40 bf16 (80B): ldmatrix conflict-free (stride 20 banks).
__global__ void __launch_bounds__(256)
gemm_bf16(const float* __restrict__ A, const float* __restrict__ B,
          float* __restrict__ C, int K, int N, const float* __restrict__ bias) {
    __shared__ __nv_bfloat16 As[2][128 * 40];
    __shared__ __nv_bfloat16 Bs[2][64 * 40];

    const int tid = threadIdx.x, lane = tid & 31, wid = tid >> 5;
    const int wm = wid >> 2, wn = wid & 3;
    const int row0 = blockIdx.y * 128, col0 = blockIdx.x * 64;

    const int lr = tid >> 3;          // load row 0..31 (x8 rows per pass)
    const int lseg = tid & 7;         // 16B segment within 128B k-row
    const uint32_t asb = smem_u32(&As[0][0]);
    const uint32_t bsb = smem_u32(&Bs[0][0]);

    float4 pa[4], pb[2];
    float acc[4][2][4];
#pragma unroll
    for (int i = 0; i < 4; i++)
#pragma unroll
        for (int j = 0; j < 2; j++)
#pragma unroll
            for (int q = 0; q < 4; q++) acc[i][j][q] = 0.f;

    const int NC = K >> 5;

    // prologue: fetch chunk 0
#pragma unroll
    for (int i = 0; i < 4; i++)
        pa[i] = *(const float4*)(A + (size_t)(row0 + lr + i * 32) * K + lseg * 4);
#pragma unroll
    for (int i = 0; i < 2; i++)
        pb[i] = *(const float4*)(B + (size_t)(col0 + lr + i * 32) * K + lseg * 4);
#pragma unroll
    for (int i = 0; i < 4; i++)
        *(uint2*)&As[0][(lr + i * 32) * 40 + lseg * 4] =
            make_uint2(pack_bf2(pa[i].x, pa[i].y), pack_bf2(pa[i].z, pa[i].w));
#pragma unroll
    for (int i = 0; i < 2; i++)
        *(uint2*)&Bs[0][(lr + i * 32) * 40 + lseg * 4] =
            make_uint2(pack_bf2(pb[i].x, pb[i].y), pack_bf2(pb[i].z, pb[i].w));
    __syncthreads();

    // per-lane ldmatrix byte offsets (within a stage, before kstep offset)
    const uint32_t a_off = (uint32_t)(wm * 64 + (lane & 15)) * 80 + (lane >> 4) * 16;
    const uint32_t b_off = (uint32_t)(wn * 16 + (lane & 7) + ((lane >> 4) << 3)) * 80
                         + ((lane >> 3) & 1) * 16;

    for (int c = 0; c < NC; c++) {
        const int s = c & 1;
        if (c + 1 < NC) {
            const int k0 = (c + 1) << 5;
#pragma unroll
            for (int i = 0; i < 4; i++)
                pa[i] = *(const float4*)(A + (size_t)(row0 + lr + i * 32) * K + k0 + lseg * 4);
#pragma unroll
            for (int i = 0; i < 2; i++)
                pb[i] = *(const float4*)(B + (size_t)(col0 + lr + i * 32) * K + k0 + lseg * 4);
        }

        const uint32_t abase = asb + (uint32_t)s * (128 * 80);
        const uint32_t bbase = bsb + (uint32_t)s * (64 * 80);
#pragma unroll
        for (int ks = 0; ks < 2; ks++) {
            uint32_t af[4][4], bf[4];
            ldsm_x4(bf[0], bf[1], bf[2], bf[3], bbase + b_off + ks * 32);
#pragma unroll
            for (int mf = 0; mf < 4; mf++)
                ldsm_x4(af[mf][0], af[mf][1], af[mf][2], af[mf][3],
                        abase + a_off + (uint32_t)mf * (16 * 80) + ks * 32);
#pragma unroll
            for (int mf = 0; mf < 4; mf++)
#pragma unroll
                for (int nf = 0; nf < 2; nf++)
                    mma16816(acc[mf][nf][0], acc[mf][nf][1], acc[mf][nf][2], acc[mf][nf][3],
                             af[mf][0], af[mf][1], af[mf][2], af[mf][3],
                             bf[nf * 2], bf[nf * 2 + 1]);
        }

        if (c + 1 < NC) {
            __syncthreads();
            const int ns = (c + 1) & 1;
#pragma unroll
            for (int i = 0; i < 4; i++)
                *(uint2*)&As[ns][(lr + i * 32) * 40 + lseg * 4] =
                    make_uint2(pack_bf2(pa[i].x, pa[i].y), pack_bf2(pa[i].z, pa[i].w));
#pragma unroll
            for (int i = 0; i < 2; i++)
                *(uint2*)&Bs[ns][(lr + i * 32) * 40 + lseg * 4] =
                    make_uint2(pack_bf2(pb[i].x, pb[i].y), pack_bf2(pb[i].z, pb[i].w));
            __syncthreads();
        }
    }

    // epilogue: direct fp32 stores (+ optional bias)
#pragma unroll
    for (int nf = 0; nf < 2; nf++) {
        int col = col0 + wn * 16 + nf * 8 + (lane & 3) * 2;
        float bx = 0.f, by = 0.f;
        if (bias) { bx = bias[col]; by = bias[col + 1]; }
#pragma unroll
        for (int mf = 0; mf < 4; mf++) {
            int r = row0 + wm * 64 + mf * 16 + (lane >> 2);
            float2 o0 = make_float2(acc[mf][nf][0] + bx, acc[mf][nf][1] + by);
            float2 o1 = make_float2(acc[mf][nf][2] + bx, acc[mf][nf][3] + by);
            *(float2*)&C[(size_t)r * N + col] = o0;
            *(float2*)&C[(size_t)(r + 8) * N + col] = o1;
        }
    }
}

// ---------------- launch ------------------------------------------------------
extern "C" void kernel_launch(void* const* d_in, const int* in_sizes, int n_in,
                              void* d_out, int out_size) {
    const float* u  = (const float*)d_in[0];
    const float* du = (const float*)d_in[1];
    const float* W  = (const float*)d_in[2];
    const float* Bw = (const float*)d_in[3];
    const float* Cw = (const float*)d_in[4];
    const float* h  = (const float*)d_in[5];
    float* y = (float*)d_out;

    float *pX, *pcat, *pb, *ps1, *ps2, *pd, *prec, *pr0, *pr1, *ppart, *pyrec;
    cudaGetSymbolAddress((void**)&pX,    g_X);
    cudaGetSymbolAddress((void**)&pcat,  g_cat);
    cudaGetSymbolAddress((void**)&pb,    g_b);
    cudaGetSymbolAddress((void**)&ps1,   g_s1);
    cudaGetSymbolAddress((void**)&ps2,   g_s2);
    cudaGetSymbolAddress((void**)&pd,    g_d);
    cudaGetSymbolAddress((void**)&prec,  g_rec);
    cudaGetSymbolAddress((void**)&pr0,   g_r0);
    cudaGetSymbolAddress((void**)&pr1,   g_r1);
    cudaGetSymbolAddress((void**)&ppart, g_part);
    cudaGetSymbolAddress((void**)&pyrec, g_yrec);

    build_X<<<dim3(64, 64), dim3(32, 8)>>>(W, pX);
    init_vec<<<H / 256, 256>>>(h, prec, pr0);
    concat_k<<<(BSZ * KCAT) / 256, 256>>>(u, du, pcat);

    // rec = h - hX + hX^2/2   (fp32; truncation error ~1e-7)
    const float coefs[2] = {-1.f, 0.5f};
    float* bufs[2] = {pr0, pr1};
    for (int s = 0; s < 2; s++) {
        gemv_part  <<<dim3(H / 256, 32), 256>>>(bufs[s & 1], pX, ppart);
        gemv_reduce<<<H / 256, 256>>>(ppart, bufs[(s + 1) & 1], prec, coefs[s]);
    }
    // yrec = rec @ Cw^T  (fp32 exact; becomes the bias of the final GEMM)
    gemv_rows<<<YD / 8, 256>>>(prec, Cw, pyrec);

    // b = cat @ Bw^T
    gemm_bf16<<<dim3(H / 64, BSZ / 128), 256>>>(pcat, Bw, pb, KCAT, H, nullptr);
    // s1 = NT(b, X) = -bX
    gemm_bf16<<<dim3(H / 64, BSZ / 128), 256>>>(pb, pX, ps1, H, H, nullptr);
    // s2 = NT(s1, X) = bX^2
    gemm_bf16<<<dim3(H / 64, BSZ / 128), 256>>>(ps1, pX, ps2, H, H, nullptr);
    // d = delta*(b + s1/2 + s2/6)
    combine_d<<<(BSZ * H) / 256, 256>>>(pb, ps1, ps2, pd);
    // y = d @ Cw^T + yrec
    gemm_bf16<<<dim3(YD / 64, BSZ / 128), 256>>>(pd, Cw, y, H, YD, pyrec);
}

// round 7
// speedup vs baseline: 5.4329x; 1.7292x over previous
#include <cuda_runtime.h>
#include <cuda_bf16.h>
#include <cstdint>

#define H      2048
#define BSZ    512
#define UD     1024
#define DUD    512
#define KCAT   1536
#define YD     1024
#define DELTA  0.01f

// ---------------- scratch (bf16 operands, fp32 vectors) ----------------------
__device__ __align__(16) __nv_bfloat16 g_Xb  [H * H];
__device__ __align__(16) __nv_bfloat16 g_cat [BSZ * KCAT];
__device__ __align__(16) __nv_bfloat16 g_Bwb [H * KCAT];
__device__ __align__(16) __nv_bfloat16 g_Cwb [YD * H];
__device__ __align__(16) __nv_bfloat16 g_b   [BSZ * H];
__device__ __align__(16) __nv_bfloat16 g_d   [BSZ * H];
__device__ float g_rec [H];
__device__ float g_r0  [H];
__device__ float g_r1  [H];
__device__ float g_part[32 * H];
__device__ float g_yrec[YD];

// ---------------- helpers -----------------------------------------------------
__device__ __forceinline__ uint32_t smem_u32(const void* p) {
    uint32_t a;
    asm("{ .reg .u64 t; cvta.to.shared.u64 t, %1; cvt.u32.u64 %0, t; }"
        : "=r"(a) : "l"(p));
    return a;
}
__device__ __forceinline__ void ldsm_x4(uint32_t& r0, uint32_t& r1, uint32_t& r2,
                                        uint32_t& r3, uint32_t a) {
    asm volatile("ldmatrix.sync.aligned.m8n8.x4.shared.b16 {%0,%1,%2,%3}, [%4];"
                 : "=r"(r0), "=r"(r1), "=r"(r2), "=r"(r3) : "r"(a));
}
__device__ __forceinline__ void mma16816(float& c0, float& c1, float& c2, float& c3,
                                         uint32_t a0, uint32_t a1, uint32_t a2, uint32_t a3,
                                         uint32_t b0, uint32_t b1) {
    asm volatile(
        "mma.sync.aligned.m16n8k16.row.col.f32.bf16.bf16.f32 "
        "{%0,%1,%2,%3},{%4,%5,%6,%7},{%8,%9},{%0,%1,%2,%3};"
        : "+f"(c0), "+f"(c1), "+f"(c2), "+f"(c3)
        : "r"(a0), "r"(a1), "r"(a2), "r"(a3), "r"(b0), "r"(b1));
}
__device__ __forceinline__ uint32_t pack_bf2(float a, float b) {
    __nv_bfloat162 p = __floats2bfloat162_rn(a, b);
    return *reinterpret_cast<uint32_t*>(&p);
}

// ---------------- prep kernels ------------------------------------------------
// X_bf16 = bf16(0.5*delta*(W - W^T))
__global__ void build_X(const float* __restrict__ W, __nv_bfloat16* __restrict__ X) {
    __shared__ float t[32][33];
    int bx = blockIdx.x * 32, by = blockIdx.y * 32;
    int tx = threadIdx.x, ty = threadIdx.y;            // 32 x 8
#pragma unroll
    for (int i = 0; i < 32; i += 8)
        t[ty + i][tx] = W[(size_t)(bx + ty + i) * H + by + tx];
    __syncthreads();
#pragma unroll
    for (int i = 0; i < 32; i += 8) {
        int r = by + ty + i, c = bx + tx;
        X[(size_t)r * H + c] =
            __float2bfloat16((0.5f * DELTA) * (W[(size_t)r * H + c] - t[tx][ty + i]));
    }
}

__global__ void conv_bf(const float* __restrict__ in, __nv_bfloat16* __restrict__ out) {
    int idx = blockIdx.x * 256 + threadIdx.x;
    float4 v = *(const float4*)(in + (size_t)idx * 4);
    *(uint2*)(out + (size_t)idx * 4) = make_uint2(pack_bf2(v.x, v.y), pack_bf2(v.z, v.w));
}

__global__ void concat_bf(const float* __restrict__ u, const float* __restrict__ du,
                          __nv_bfloat16* __restrict__ cat) {
    int idx = blockIdx.x * 256 + threadIdx.x;
    int i = idx / KCAT;
    int k = idx - i * KCAT;
    cat[idx] = __float2bfloat16((k < DUD) ? du[i * DUD + k] : u[i * UD + (k - DUD)]);
}

__global__ void init_vec(const float* __restrict__ h,
                         float* __restrict__ rec, float* __restrict__ r0) {
    int j = blockIdx.x * 256 + threadIdx.x;
    float v = h[j];
    rec[j] = v;
    r0[j] = v;
}

// ---------------- GEMV chain: rec = h - hX + hX^2/2  (bf16 X, fp32 acc) -------
__global__ void gemv_part(const float* __restrict__ x, const __nv_bfloat16* __restrict__ Xb,
                          float* __restrict__ part) {
    __shared__ float xs[64];
    int j = blockIdx.x * 256 + threadIdx.x;            // column-pair index
    int k0 = blockIdx.y * 64;
    if (threadIdx.x < 64) xs[threadIdx.x] = x[k0 + threadIdx.x];
    __syncthreads();
    float a0 = 0.f, a1 = 0.f;
#pragma unroll 16
    for (int k = 0; k < 64; k++) {
        __nv_bfloat162 v = *(const __nv_bfloat162*)(Xb + (size_t)(k0 + k) * H + 2 * j);
        a0 += xs[k] * __low2float(v);
        a1 += xs[k] * __high2float(v);
    }
    *(float2*)(part + blockIdx.y * H + 2 * j) = make_float2(a0, a1);
}

__global__ void gemv_reduce(const float* __restrict__ part, float* __restrict__ out,
                            float* __restrict__ rec, float coef) {
    int j = blockIdx.x * 256 + threadIdx.x;
    float s = 0.f;
#pragma unroll
    for (int c = 0; c < 32; c++) s += part[c * H + j];
    out[j] = s;
    rec[j] += coef * s;
}

// yrec[j] = sum_k rec[k] * Cw[j*H + k]   (fp32 exact: dominant term of y)
__global__ void gemv_rows(const float* __restrict__ rec, const float* __restrict__ Cw,
                          float* __restrict__ yrec) {
    int row = blockIdx.x * 8 + (threadIdx.x >> 5);
    int lane = threadIdx.x & 31;
    const float* cr = Cw + (size_t)row * H;
    float s = 0.f;
#pragma unroll
    for (int i = 0; i < 16; i++) {
        float4 c = *(const float4*)(cr + lane * 4 + i * 128);
        float4 r = *(const float4*)(rec + lane * 4 + i * 128);
        s += c.x * r.x + c.y * r.y + c.z * r.z + c.w * r.w;
    }
#pragma unroll
    for (int o = 16; o > 0; o >>= 1) s += __shfl_xor_sync(0xffffffffu, s, o);
    if (lane == 0) yrec[row] = s;
}

// ---------------- bf16 mma.sync NT GEMM (bf16 in, bf16/fp32 out) --------------
// C[m,n] = sum_k A[m*K+k]*B[n*K+k].  CTA tile MT x 64, K-chunk 64, 8 warps
// (2m x 4n), warp tile (MT/2) x 16. SMEM rows 144B (conflict-free ldmatrix).
// MODE 0: C = bf16(acc)            (b-GEMM)
// MODE 1: C = bf16(DELTA*(aux + acc/2))   (s1 -> d fused)
// MODE 2: C = fp32(acc + bias[n])  (y-GEMM)
template <int MT, int MODE>
__global__ void __launch_bounds__(256)
gemm_bf(const __nv_bfloat16* __restrict__ A, const __nv_bfloat16* __restrict__ B,
        void* __restrict__ Cout, int K, int N,
        const __nv_bfloat16* __restrict__ aux, const float* __restrict__ bias) {
    extern __shared__ __align__(16) char smem[];
    constexpr int AST = MT * 144;                      // A stage bytes
    constexpr int BST = 64 * 144;
    constexpr int MF = MT / 32;                        // 16-row frags per warp
    constexpr int APASS = MT / 32;                     // A load passes

    const int tid = threadIdx.x, lane = tid & 31, wid = tid >> 5;
    const int wm = wid >> 2, wn = wid & 3;
    const int row0 = blockIdx.y * MT, col0 = blockIdx.x * 64;

    const int lr = tid >> 3;                           // 0..31
    const int lseg = tid & 7;                          // 16B segment of 128B row
    const uint32_t asb = smem_u32(smem);
    const uint32_t bsb = asb + 2 * AST;

    const __nv_bfloat16* Ag = A + (size_t)(row0 + lr) * K + lseg * 8;
    const __nv_bfloat16* Bg = B + (size_t)(col0 + lr) * K + lseg * 8;

    uint4 pa[APASS], pb[2];
    float acc[MF][2][4];
#pragma unroll
    for (int i = 0; i < MF; i++)
#pragma unroll
        for (int j = 0; j < 2; j++)
#pragma unroll
            for (int q = 0; q < 4; q++) acc[i][j][q] = 0.f;

    const int NC = K >> 6;

    // prologue: chunk 0
#pragma unroll
    for (int i = 0; i < APASS; i++) pa[i] = *(const uint4*)(Ag + (size_t)i * 32 * K);
#pragma unroll
    for (int i = 0; i < 2; i++)     pb[i] = *(const uint4*)(Bg + (size_t)i * 32 * K);
#pragma unroll
    for (int i = 0; i < APASS; i++)
        *(uint4*)(smem + (lr + i * 32) * 144 + lseg * 16) = pa[i];
#pragma unroll
    for (int i = 0; i < 2; i++)
        *(uint4*)(smem + 2 * AST + (lr + i * 32) * 144 + lseg * 16) = pb[i];
    __syncthreads();

    const uint32_t a_off = (uint32_t)(wm * (MT / 2) + (lane & 15)) * 144 + (lane >> 4) * 16;
    const uint32_t b_off = (uint32_t)(wn * 16 + (lane & 7) + ((lane >> 4) << 3)) * 144
                         + ((lane >> 3) & 1) * 16;

    for (int c = 0; c < NC; c++) {
        const int s = c & 1;
        if (c + 1 < NC) {
            const int k0 = (c + 1) << 6;
#pragma unroll
            for (int i = 0; i < APASS; i++)
                pa[i] = *(const uint4*)(Ag + (size_t)i * 32 * K + k0);
#pragma unroll
            for (int i = 0; i < 2; i++)
                pb[i] = *(const uint4*)(Bg + (size_t)i * 32 * K + k0);
        }

        const uint32_t abase = asb + (uint32_t)s * AST;
        const uint32_t bbase = bsb + (uint32_t)s * BST;
#pragma unroll
        for (int ks = 0; ks < 4; ks++) {
            uint32_t af[MF][4], bf[4];
            ldsm_x4(bf[0], bf[1], bf[2], bf[3], bbase + b_off + ks * 32);
#pragma unroll
            for (int mf = 0; mf < MF; mf++)
                ldsm_x4(af[mf][0], af[mf][1], af[mf][2], af[mf][3],
                        abase + a_off + (uint32_t)mf * (16 * 144) + ks * 32);
#pragma unroll
            for (int mf = 0; mf < MF; mf++)
#pragma unroll
                for (int nf = 0; nf < 2; nf++)
                    mma16816(acc[mf][nf][0], acc[mf][nf][1], acc[mf][nf][2], acc[mf][nf][3],
                             af[mf][0], af[mf][1], af[mf][2], af[mf][3],
                             bf[nf * 2], bf[nf * 2 + 1]);
        }

        if (c + 1 < NC) {
            __syncthreads();
            const int ns = (c + 1) & 1;
#pragma unroll
            for (int i = 0; i < APASS; i++)
                *(uint4*)(smem + ns * AST + (lr + i * 32) * 144 + lseg * 16) = pa[i];
#pragma unroll
            for (int i = 0; i < 2; i++)
                *(uint4*)(smem + 2 * AST + ns * BST + (lr + i * 32) * 144 + lseg * 16) = pb[i];
            __syncthreads();
        }
    }

    // epilogue
#pragma unroll
    for (int nf = 0; nf < 2; nf++) {
        const int col = col0 + wn * 16 + nf * 8 + (lane & 3) * 2;
        float bx = 0.f, by = 0.f;
        if (MODE == 2) { bx = bias[col]; by = bias[col + 1]; }
#pragma unroll
        for (int mf = 0; mf < MF; mf++) {
            const int r = row0 + wm * (MT / 2) + mf * 16 + (lane >> 2);
#pragma unroll
            for (int half = 0; half < 2; half++) {
                const int rr = r + half * 8;
                const float v0 = acc[mf][nf][half * 2 + 0];
                const float v1 = acc[mf][nf][half * 2 + 1];
                if (MODE == 0) {
                    *(uint32_t*)((__nv_bfloat16*)Cout + (size_t)rr * N + col) =
                        pack_bf2(v0, v1);
                } else if (MODE == 1) {
                    __nv_bfloat162 bv =
                        *(const __nv_bfloat162*)(aux + (size_t)rr * N + col);
                    *(uint32_t*)((__nv_bfloat16*)Cout + (size_t)rr * N + col) =
                        pack_bf2(DELTA * (__low2float(bv)  + 0.5f * v0),
                                 DELTA * (__high2float(bv) + 0.5f * v1));
                } else {
                    *(float2*)((float*)Cout + (size_t)rr * N + col) =
                        make_float2(v0 + bx, v1 + by);
                }
            }
        }
    }
}

// ---------------- launch ------------------------------------------------------
extern "C" void kernel_launch(void* const* d_in, const int* in_sizes, int n_in,
                              void* d_out, int out_size) {
    const float* u  = (const float*)d_in[0];
    const float* du = (const float*)d_in[1];
    const float* W  = (const float*)d_in[2];
    const float* Bw = (const float*)d_in[3];
    const float* Cw = (const float*)d_in[4];
    const float* h  = (const float*)d_in[5];
    float* y = (float*)d_out;

    __nv_bfloat16 *pXb, *pcat, *pBwb, *pCwb, *pb, *pd;
    float *prec, *pr0, *pr1, *ppart, *pyrec;
    cudaGetSymbolAddress((void**)&pXb,   g_Xb);
    cudaGetSymbolAddress((void**)&pcat,  g_cat);
    cudaGetSymbolAddress((void**)&pBwb,  g_Bwb);
    cudaGetSymbolAddress((void**)&pCwb,  g_Cwb);
    cudaGetSymbolAddress((void**)&pb,    g_b);
    cudaGetSymbolAddress((void**)&pd,    g_d);
    cudaGetSymbolAddress((void**)&prec,  g_rec);
    cudaGetSymbolAddress((void**)&pr0,   g_r0);
    cudaGetSymbolAddress((void**)&pr1,   g_r1);
    cudaGetSymbolAddress((void**)&ppart, g_part);
    cudaGetSymbolAddress((void**)&pyrec, g_yrec);

    constexpr int SM128 = 2 * (128 * 144) + 2 * (64 * 144);   // 55296
    constexpr int SM64  = 2 * (64 * 144) + 2 * (64 * 144);    // 36864
    cudaFuncSetAttribute(gemm_bf<128, 0>, cudaFuncAttributeMaxDynamicSharedMemorySize, SM128);
    cudaFuncSetAttribute(gemm_bf<128, 1>, cudaFuncAttributeMaxDynamicSharedMemorySize, SM128);
    cudaFuncSetAttribute(gemm_bf<64, 2>,  cudaFuncAttributeMaxDynamicSharedMemorySize, SM64);

    // operand prep (all bf16)
    build_X<<<dim3(64, 64), dim3(32, 8)>>>(W, pXb);
    conv_bf<<<(H * KCAT) / 1024, 256>>>(Bw, pBwb);
    conv_bf<<<(YD * H) / 1024, 256>>>(Cw, pCwb);
    concat_bf<<<(BSZ * KCAT) / 256, 256>>>(u, du, pcat);
    init_vec<<<H / 256, 256>>>(h, prec, pr0);

    // rec = h - hX + hX^2/2   (fp32 accumulate over bf16 X)
    const float coefs[2] = {-1.f, 0.5f};
    float* bufs[2] = {pr0, pr1};
    for (int s = 0; s < 2; s++) {
        gemv_part  <<<dim3(H / 512, 32), 256>>>(bufs[s & 1], pXb, ppart);
        gemv_reduce<<<H / 256, 256>>>(ppart, bufs[(s + 1) & 1], prec, coefs[s]);
    }
    // yrec = rec @ Cw^T  (fp32 exact; bias of the final GEMM)
    gemv_rows<<<YD / 8, 256>>>(prec, Cw, pyrec);

    // b = cat @ Bw^T  -> bf16
    gemm_bf<128, 0><<<dim3(H / 64, BSZ / 128), 256, SM128>>>(
        pcat, pBwb, pb, KCAT, H, nullptr, nullptr);
    // d = delta*(b + NT(b,X)/2)  -> bf16   (s1 GEMM + combine fused)
    gemm_bf<128, 1><<<dim3(H / 64, BSZ / 128), 256, SM128>>>(
        pb, pXb, pd, H, H, pb, nullptr);
    // y = d @ Cw^T + yrec  -> fp32
    gemm_bf<64, 2><<<dim3(YD / 64, BSZ / 64), 256, SM64>>>(
        pd, pCwb, y, H, YD, nullptr, pyrec);
}